// round 17
// baseline (speedup 1.0000x reference)
#include <cuda_runtime.h>
#include <cuda_fp16.h>
#include <cstdint>

#define DIM 128
#define NTH 512
#define WARPS 16
#define PI_F 3.14159265358979323846f

// ---- smem: W tiles (packed 8x8-matrix layout) + biases + per-warp h ----
#define OFF_W1  0
#define OFF_W2  32768
#define OFF_B1  65536
#define OFF_B2  66048
#define OFF_H   66560           // 16 warps x 8192 B
#define SMEM_TOTAL (66560 + 16 * 8192)

// W packed layout: 16x16 grid of 8x8 fp16 matrices; matrix (nt,kt) at ((kt*16)+nt)*128
__device__ __forceinline__ uint32_t w_off(int n, int k) {
    return (uint32_t)((((k >> 3) << 4) + (n >> 3)) * 128 + (n & 7) * 16 + (k & 7) * 2);
}
// per-warp h packed layout: 4x16 grid (32 rows x 128 k); matrix (mr,kt) at ((kt*4)+mr)*128
__device__ __forceinline__ uint32_t h_off(int row, int col) {
    return (uint32_t)((((col >> 3) << 2) + (row >> 3)) * 128 + (row & 7) * 16 + (col & 7) * 2);
}

__device__ __forceinline__ uint32_t smem_u32(const void* p) {
    uint32_t a;
    asm("{ .reg .u64 t; cvta.to.shared.u64 t, %1; cvt.u32.u64 %0, t; }" : "=r"(a) : "l"(p));
    return a;
}

__device__ __forceinline__ void ldsm4(uint32_t& r0, uint32_t& r1, uint32_t& r2, uint32_t& r3,
                                      uint32_t addr) {
    asm volatile("ldmatrix.sync.aligned.m8n8.x4.shared.b16 {%0,%1,%2,%3}, [%4];"
                 : "=r"(r0), "=r"(r1), "=r"(r2), "=r"(r3) : "r"(addr));
}

__device__ __forceinline__ void mma16816(float* c, const uint32_t* a, uint32_t b0, uint32_t b1) {
    asm volatile(
        "mma.sync.aligned.m16n8k16.row.col.f32.f16.f16.f32 "
        "{%0,%1,%2,%3}, {%4,%5,%6,%7}, {%8,%9}, {%0,%1,%2,%3};"
        : "+f"(c[0]), "+f"(c[1]), "+f"(c[2]), "+f"(c[3])
        : "r"(a[0]), "r"(a[1]), "r"(a[2]), "r"(a[3]), "r"(b0), "r"(b1));
}

__device__ __forceinline__ uint32_t pack2h(float x0, float x1) {
    uint32_t r;
    asm("cvt.rn.f16x2.f32 %0, %1, %2;" : "=r"(r) : "f"(x1), "f"(x0));
    return r;
}

// silu on packed fp16 pair via tanh.approx.f16x2 (hidden layer)
__device__ __forceinline__ uint32_t h2_silu(float z0, float z1) {
    const uint32_t zh = pack2h(z0, z1);
    const uint32_t half2c = 0x38003800u;
    uint32_t t, s, r;
    asm("mul.rn.f16x2 %0, %1, %2;" : "=r"(t) : "r"(zh), "r"(half2c));
    asm("tanh.approx.f16x2 %0, %1;" : "=r"(t) : "r"(t));
    asm("fma.rn.f16x2 %0, %1, %2, %2;" : "=r"(s) : "r"(t), "r"(half2c));
    asm("mul.rn.f16x2 %0, %1, %2;" : "=r"(r) : "r"(zh), "r"(s));
    return r;
}

// fp32 silu via tanh.approx.f32 (output layer)
__device__ __forceinline__ float silu_f(float z) {
    float th;
    const float zh = 0.5f * z;
    asm("tanh.approx.f32 %0, %1;" : "=f"(th) : "f"(zh));
    return zh * (1.0f + th);
}

__global__ void __launch_bounds__(NTH, 1)
fused_timestep_mlp_v17(const float* __restrict__ t,
                       const float* __restrict__ W1,
                       const float* __restrict__ b1,
                       const float* __restrict__ W2,
                       const float* __restrict__ b2,
                       float* __restrict__ out,
                       int n_chunks) {
    extern __shared__ char sm[];
    const uint32_t sb = smem_u32(sm);
    const int tid = threadIdx.x;
    const int wid = tid >> 5;
    const int lane = tid & 31;

    // ---- weight init: packed fp16 tiles; biases ----
    for (int e = tid * 4; e < DIM * DIM; e += NTH * 4) {
        const int row = e >> 7, k = e & 127;
        const float4 v1 = *(const float4*)(W1 + e);
        *(uint32_t*)(sm + OFF_W1 + w_off(row, k))     = pack2h(v1.x, v1.y);
        *(uint32_t*)(sm + OFF_W1 + w_off(row, k + 2)) = pack2h(v1.z, v1.w);
        const float4 v2 = *(const float4*)(W2 + e);
        *(uint32_t*)(sm + OFF_W2 + w_off(row, k))     = pack2h(v2.x, v2.y);
        *(uint32_t*)(sm + OFF_W2 + w_off(row, k + 2)) = pack2h(v2.z, v2.w);
    }
    if (tid < 128)      ((float*)(sm + OFF_B1))[tid] = b1[tid];
    else if (tid < 256) ((float*)(sm + OFF_B2))[tid - 128] = b2[tid - 128];
    __syncthreads();  // only full-CTA sync

    const float* sB1 = (const float*)(sm + OFF_B1);
    const float* sB2 = (const float*)(sm + OFF_B2);
    const uint32_t hbase = sb + OFF_H + (uint32_t)wid * 8192;
    char* hmem = sm + OFF_H + wid * 8192;

    // lane geometry
    const int r0 = lane >> 2;        // frag row within 16 (and +8)
    const int kp = (lane & 3) * 2;   // frag col-pair base
    const int g = lane >> 3, i = lane & 7;
    // W ldsm4 per-lane offset (as v16)
    const uint32_t tileOff = ((uint32_t)(g & 1) << 11) | ((uint32_t)(g >> 1) << 7)
                           | ((uint32_t)i << 4);
    // h (A-operand) ldsm4 per-lane offset: a0/a1 = m-low/high k-low, a2/a3 = k-high
    const uint32_t laneAoff = ((uint32_t)(g >> 1) << 9) | ((uint32_t)(g & 1) << 7)
                            | ((uint32_t)i << 4);

    for (int chunk = blockIdx.x * WARPS + wid; chunk < n_chunks;
         chunk += gridDim.x * WARPS) {
        const int rowBase = chunk * 32;

        // ---- emb A-frags via rotation recurrence: ea[mt][ks][4] (per-mt passes) ----
        uint32_t ea[2][8][4];
#pragma unroll
        for (int mt = 0; mt < 2; ++mt) {
            float C1a[2], S1a[2], C1b[2], S1b[2];
            float C2a[2], S2a[2], C2b[2], S2b[2];
            float R1c[2], R1s[2], R2c[2], R2s[2];
            float q1c[2], q1s[2], q2c[2], q2s[2];
#pragma unroll
            for (int u = 0; u < 2; ++u) {
                const float tv = t[rowBase + mt * 16 + r0 + u * 8];
                const float p1 = tv * (PI_F / 128.0f);
                const float p2 = (1.0f - tv) * (PI_F / 128.0f);
                const float dk = (float)kp;
                C1a[u] = tv * __cosf(dk * p1);          S1a[u] = tv * __sinf(dk * p1);
                C1b[u] = tv * __cosf((dk + 8.0f) * p1); S1b[u] = tv * __sinf((dk + 8.0f) * p1);
                C2a[u] = tv * __cosf(dk * p2);          S2a[u] = tv * __sinf(dk * p2);
                C2b[u] = tv * __cosf((dk + 8.0f) * p2); S2b[u] = tv * __sinf((dk + 8.0f) * p2);
                R1c[u] = __cosf(16.0f * p1); R1s[u] = __sinf(16.0f * p1);
                R2c[u] = __cosf(16.0f * p2); R2s[u] = __sinf(16.0f * p2);
                q1c[u] = __cosf(p1);         q1s[u] = __sinf(p1);
                q2c[u] = __cosf(p2);         q2s[u] = __sinf(p2);
            }
#pragma unroll
            for (int ks = 0; ks < 8; ++ks) {
#pragma unroll
                for (int u = 0; u < 2; ++u) {
                    const float e0 = C1a[u] + S2a[u];
                    const float e1 = (C1a[u] * q1c[u] - S1a[u] * q1s[u])
                                   + (S2a[u] * q2c[u] + C2a[u] * q2s[u]);
                    const float e8 = C1b[u] + S2b[u];
                    const float e9 = (C1b[u] * q1c[u] - S1b[u] * q1s[u])
                                   + (S2b[u] * q2c[u] + C2b[u] * q2s[u]);
                    ea[mt][ks][u]     = pack2h(e0, e1);
                    ea[mt][ks][2 + u] = pack2h(e8, e9);
                    float nc, ns;
                    nc = C1a[u] * R1c[u] - S1a[u] * R1s[u];
                    ns = S1a[u] * R1c[u] + C1a[u] * R1s[u];
                    C1a[u] = nc; S1a[u] = ns;
                    nc = C1b[u] * R1c[u] - S1b[u] * R1s[u];
                    ns = S1b[u] * R1c[u] + C1b[u] * R1s[u];
                    C1b[u] = nc; S1b[u] = ns;
                    nc = C2a[u] * R2c[u] - S2a[u] * R2s[u];
                    ns = S2a[u] * R2c[u] + C2a[u] * R2s[u];
                    C2a[u] = nc; S2a[u] = ns;
                    nc = C2b[u] * R2c[u] - S2b[u] * R2s[u];
                    ns = S2b[u] * R2c[u] + C2b[u] * R2s[u];
                    C2b[u] = nc; S2b[u] = ns;
                }
            }
        }

        // ======== GEMM1: 4 n-quarter passes; W1 ldsm shared by both m-tiles ========
#pragma unroll
        for (int nq = 0; nq < 4; ++nq) {
            float acc[2][4][4];
#pragma unroll
            for (int mt = 0; mt < 2; ++mt)
#pragma unroll
                for (int nt = 0; nt < 4; ++nt)
#pragma unroll
                    for (int q = 0; q < 4; ++q) acc[mt][nt][q] = 0.0f;

#pragma unroll
            for (int ks = 0; ks < 8; ++ks) {
#pragma unroll
                for (int np = 0; np < 2; ++np) {
                    const int npg = nq * 2 + np;
                    uint32_t b[4];
                    ldsm4(b[0], b[1], b[2], b[3],
                          sb + OFF_W1 + ((uint32_t)ks << 12) + ((uint32_t)npg << 8) + tileOff);
#pragma unroll
                    for (int mt = 0; mt < 2; ++mt) {
                        mma16816(acc[mt][2 * np],     ea[mt][ks], b[0], b[1]);
                        mma16816(acc[mt][2 * np + 1], ea[mt][ks], b[2], b[3]);
                    }
                }
            }

            // epi1: bias + silu(f16x2) -> warp-private h smem
#pragma unroll
            for (int nt = 0; nt < 4; ++nt) {
                const int c = nq * 32 + nt * 8 + kp;
                const float2 bb = *(const float2*)(sB1 + c);
#pragma unroll
                for (int mt = 0; mt < 2; ++mt) {
                    const float* a4 = acc[mt][nt];
                    const int rr = mt * 16 + r0;
                    *(uint32_t*)(hmem + h_off(rr, c))     = h2_silu(a4[0] + bb.x, a4[1] + bb.y);
                    *(uint32_t*)(hmem + h_off(rr + 8, c)) = h2_silu(a4[2] + bb.x, a4[3] + bb.y);
                }
            }
        }
        __syncwarp();

        // ======== GEMM2: 2 n-half passes; W2 ldsm shared; h A-frags from smem ========
#pragma unroll
        for (int nh = 0; nh < 2; ++nh) {
            float acc[2][8][4];
#pragma unroll
            for (int mt = 0; mt < 2; ++mt)
#pragma unroll
                for (int nt = 0; nt < 8; ++nt)
#pragma unroll
                    for (int q = 0; q < 4; ++q) acc[mt][nt][q] = 0.0f;

#pragma unroll
            for (int ks = 0; ks < 8; ++ks) {
                uint32_t a[2][4];
#pragma unroll
                for (int mt = 0; mt < 2; ++mt)
                    ldsm4(a[mt][0], a[mt][1], a[mt][2], a[mt][3],
                          hbase + ((uint32_t)ks << 10) + ((uint32_t)mt << 8) + laneAoff);
#pragma unroll
                for (int np = 0; np < 4; ++np) {
                    const int npg = nh * 4 + np;
                    uint32_t b[4];
                    ldsm4(b[0], b[1], b[2], b[3],
                          sb + OFF_W2 + ((uint32_t)ks << 12) + ((uint32_t)npg << 8) + tileOff);
#pragma unroll
                    for (int mt = 0; mt < 2; ++mt) {
                        mma16816(acc[mt][2 * np],     a[mt], b[0], b[1]);
                        mma16816(acc[mt][2 * np + 1], a[mt], b[2], b[3]);
                    }
                }
            }

            // epi2: bias + silu (tanh.f32) -> gmem
#pragma unroll
            for (int mt = 0; mt < 2; ++mt) {
                float* o0 = out + (size_t)(rowBase + mt * 16 + r0) * DIM;
                float* o1 = out + (size_t)(rowBase + mt * 16 + r0 + 8) * DIM;
#pragma unroll
                for (int nt = 0; nt < 8; ++nt) {
                    const int c = nh * 64 + nt * 8 + kp;
                    const float2 bb = *(const float2*)(sB2 + c);
                    const float* a4 = acc[mt][nt];
                    *(float2*)(o0 + c) = make_float2(silu_f(a4[0] + bb.x), silu_f(a4[1] + bb.y));
                    *(float2*)(o1 + c) = make_float2(silu_f(a4[2] + bb.x), silu_f(a4[3] + bb.y));
                }
            }
        }
        __syncwarp();  // GEMM2 h reads done before next chunk's epi1 overwrites
    }
}

extern "C" void kernel_launch(void* const* d_in, const int* in_sizes, int n_in,
                              void* d_out, int out_size) {
    const float* t  = (const float*)d_in[0];
    const float* W1 = (const float*)d_in[1];
    const float* b1 = (const float*)d_in[2];
    const float* W2 = (const float*)d_in[3];
    const float* b2 = (const float*)d_in[4];
    float* out = (float*)d_out;

    const int B = in_sizes[0];
    const int n_chunks = B / 32;

    int nsm = 148;
    cudaDeviceGetAttribute(&nsm, cudaDevAttrMultiProcessorCount, 0);

    cudaFuncSetAttribute(fused_timestep_mlp_v17,
                         cudaFuncAttributeMaxDynamicSharedMemorySize, SMEM_TOTAL);

    fused_timestep_mlp_v17<<<nsm, NTH, SMEM_TOTAL>>>(t, W1, b1, W2, b2, out, n_chunks);
}